// round 1
// baseline (speedup 1.0000x reference)
#include <cuda_runtime.h>
#include <math.h>
#include <float.h>

// Problem constants
#define N_X    2048
#define M_BUF  131072
#define D_DIM  64
#define KK     11                 // K+1 smallest kept per row
#define SPLITS 8
#define MSPLIT (M_BUF / SPLITS)   // 16384
#define TB     64                 // buf tile rows per iteration
#define BX     64                 // x rows per block
#define NTILES (MSPLIT / TB)      // 256
#define LDSTR  68                 // shared tile row stride in floats (pad for banks)

// Scratch (no allocations allowed -> device globals)
__device__ float g_bn2[M_BUF];
__device__ float g_cand[(size_t)N_X * SPLITS * KK];

// ---------------------------------------------------------------------------
// Kernel 1: per-row squared norms of buf. One warp per row, float2 per lane.
// ---------------------------------------------------------------------------
__global__ void bn2_kernel(const float* __restrict__ buf) {
    int warp = (blockIdx.x * blockDim.x + threadIdx.x) >> 5;
    int lane = threadIdx.x & 31;
    if (warp >= M_BUF) return;
    const float2* p = reinterpret_cast<const float2*>(buf + (size_t)warp * D_DIM);
    float2 v = p[lane];
    float s = v.x * v.x + v.y * v.y;
    #pragma unroll
    for (int o = 16; o > 0; o >>= 1) s += __shfl_xor_sync(0xffffffffu, s, o);
    if (lane == 0) g_bn2[warp] = s;
}

// ---------------------------------------------------------------------------
// Kernel 2: main fused distance + running top-11 kernel.
// Grid: (32 x-row blocks, 8 buf splits). 256 threads = 16 (i) x 16 (j).
// Thread (i,j): x rows {i, i+16, i+32, i+48}, buf rows {j, j+16, j+32, j+48}
// within each 64-row tile (stride-16 mapping keeps LDS bank conflicts <= 2-way).
// Packed fp32x2 FMA accumulators (fma.rn.f32x2) for 2x fp32 throughput.
// ---------------------------------------------------------------------------
extern __shared__ float smem[];
// float offsets inside dynamic smem:
//   xs   : [0,     4352)   64 x 68
//   bs0  : [4352,  8704)   64 x 68
//   bs1  : [8704, 13056)   64 x 68
//   xn2  : [13056,13120)
// merge phase aliases [0, 11264) as cand[64][16][11]
#define SMEM_FLOATS 13120

#define FMA2(acc, av, bv) \
    asm("fma.rn.f32x2 %0, %1, %2, %0;" : "+l"(acc) : "l"(av), "l"(bv))

__device__ __forceinline__ void prefetch_tile(const float* __restrict__ buf,
                                              int jrow0, float* dst, int tid) {
    #pragma unroll
    for (int ii = 0; ii < 4; ii++) {
        int idx = tid + 256 * ii;          // 1024 quads total
        int r = idx >> 4, q = idx & 15;
        unsigned ds = (unsigned)__cvta_generic_to_shared(dst + r * LDSTR + q * 4);
        const float* src = buf + (size_t)(jrow0 + r) * D_DIM + q * 4;
        asm volatile("cp.async.cg.shared.global [%0], [%1], 16;\n" :: "r"(ds), "l"(src));
    }
}

__global__ void __launch_bounds__(256, 2)
pbe_main(const float* __restrict__ x, const float* __restrict__ buf) {
    float* xs   = smem;
    float* bs0  = smem + 4352;
    float* bs1  = smem + 8704;
    float* sxn2 = smem + 13056;

    const int tid = threadIdx.x;
    const int i = tid >> 4;     // 0..15 x group
    const int j = tid & 15;     // 0..15 buf group
    const int xbase  = blockIdx.x * BX;       // 0..31 blocks
    const int split  = blockIdx.y;            // 0..7
    const int jbase0 = split * MSPLIT;

    // ---- load x tile (once) ----
    #pragma unroll
    for (int ii = 0; ii < 4; ii++) {
        int idx = tid + 256 * ii;
        int r = idx >> 4, q = idx & 15;
        float4 v = *reinterpret_cast<const float4*>(x + (size_t)(xbase + r) * D_DIM + q * 4);
        *reinterpret_cast<float4*>(xs + r * LDSTR + q * 4) = v;
    }
    __syncthreads();
    if (tid < BX) {
        float s = 0.f;
        #pragma unroll
        for (int k = 0; k < D_DIM; k++) { float v = xs[tid * LDSTR + k]; s += v * v; }
        sxn2[tid] = s;
    }
    __syncthreads();

    float xn2[4];
    #pragma unroll
    for (int a = 0; a < 4; a++) xn2[a] = sxn2[i + a * 16];

    // per-thread running top-11 per owned x row (local memory; max-replacement)
    float tk[4][KK];
    float thr[4];
    int   mxi[4];
    #pragma unroll
    for (int a = 0; a < 4; a++) {
        for (int s = 0; s < KK; s++) tk[a][s] = FLT_MAX;
        thr[a] = FLT_MAX; mxi[a] = 0;
    }

    // ---- double-buffered mainloop over buf tiles ----
    prefetch_tile(buf, jbase0, bs0, tid);
    asm volatile("cp.async.commit_group;\n");

    for (int t = 0; t < NTILES; t++) {
        if (t + 1 < NTILES) {
            prefetch_tile(buf, jbase0 + (t + 1) * TB, ((t + 1) & 1) ? bs1 : bs0, tid);
            asm volatile("cp.async.commit_group;\n");
            asm volatile("cp.async.wait_group 1;\n");
        } else {
            asm volatile("cp.async.wait_group 0;\n");
        }
        __syncthreads();

        const float* bt = (t & 1) ? bs1 : bs0;
        const int jr0 = jbase0 + t * TB;

        float bn2v[4];
        #pragma unroll
        for (int b = 0; b < 4; b++) bn2v[b] = __ldg(&g_bn2[jr0 + j + b * 16]);

        unsigned long long acc[4][4];
        #pragma unroll
        for (int a = 0; a < 4; a++)
            #pragma unroll
            for (int b = 0; b < 4; b++) acc[a][b] = 0ULL;

        #pragma unroll
        for (int k4 = 0; k4 < 16; k4++) {
            ulonglong2 xa[4], bb[4];
            #pragma unroll
            for (int a = 0; a < 4; a++)
                xa[a] = *reinterpret_cast<const ulonglong2*>(xs + (i + a * 16) * LDSTR + k4 * 4);
            #pragma unroll
            for (int b = 0; b < 4; b++)
                bb[b] = *reinterpret_cast<const ulonglong2*>(bt + (j + b * 16) * LDSTR + k4 * 4);
            #pragma unroll
            for (int a = 0; a < 4; a++)
                #pragma unroll
                for (int b = 0; b < 4; b++) {
                    FMA2(acc[a][b], xa[a].x, bb[b].x);
                    FMA2(acc[a][b], xa[a].y, bb[b].y);
                }
        }

        // candidates -> running top-11
        #pragma unroll
        for (int a = 0; a < 4; a++) {
            #pragma unroll
            for (int b = 0; b < 4; b++) {
                float lo = __uint_as_float((unsigned)acc[a][b]);
                float hi = __uint_as_float((unsigned)(acc[a][b] >> 32));
                float d2 = fmaf(-2.f, lo + hi, xn2[a] + bn2v[b]);
                d2 = fmaxf(d2, 0.f);
                if (d2 < thr[a]) {
                    tk[a][mxi[a]] = d2;
                    float m = tk[a][0]; int mi = 0;
                    #pragma unroll
                    for (int s = 1; s < KK; s++)
                        if (tk[a][s] > m) { m = tk[a][s]; mi = s; }
                    thr[a] = m; mxi[a] = mi;
                }
            }
        }
        __syncthreads();   // protect bt slot before next prefetch overwrites it
    }

    // ---- block-level merge: 16 j-threads per x row -> per-block top-11 ----
    float* csh = smem;     // alias: [64 rows][16 j][11]
    #pragma unroll
    for (int a = 0; a < 4; a++)
        #pragma unroll
        for (int s = 0; s < KK; s++)
            csh[(i + a * 16) * (16 * KK) + j * KK + s] = tk[a][s];
    __syncthreads();

    if (tid < BX) {
        const float* src = csh + tid * (16 * KK);
        float best[KK];
        float m = FLT_MAX; int mi = 0;
        #pragma unroll
        for (int s = 0; s < KK; s++) best[s] = FLT_MAX;
        for (int s = 0; s < 16 * KK; s++) {
            float v = src[s];
            if (v < m) {
                best[mi] = v;
                float mm = best[0]; int mj = 0;
                #pragma unroll
                for (int q = 1; q < KK; q++)
                    if (best[q] > mm) { mm = best[q]; mj = q; }
                m = mm; mi = mj;
            }
        }
        float* dst = g_cand + ((size_t)(xbase + tid) * SPLITS + split) * KK;
        #pragma unroll
        for (int s = 0; s < KK; s++) dst[s] = best[s];
    }
}

// ---------------------------------------------------------------------------
// Kernel 3: merge 8 splits x 11 candidates per row, drop min, mean(sqrt), log1p
// ---------------------------------------------------------------------------
__global__ void merge_kernel(float* __restrict__ out) {
    int row = blockIdx.x * blockDim.x + threadIdx.x;
    if (row >= N_X) return;
    const float* src = g_cand + (size_t)row * SPLITS * KK;
    float best[KK];
    float m = FLT_MAX; int mi = 0;
    #pragma unroll
    for (int s = 0; s < KK; s++) best[s] = FLT_MAX;
    for (int s = 0; s < SPLITS * KK; s++) {
        float v = src[s];
        if (v < m) {
            best[mi] = v;
            float mm = best[0]; int mj = 0;
            #pragma unroll
            for (int q = 1; q < KK; q++)
                if (best[q] > mm) { mm = best[q]; mj = q; }
            m = mm; mi = mj;
        }
    }
    float ssum = 0.f, rmin = FLT_MAX;
    #pragma unroll
    for (int s = 0; s < KK; s++) {
        float r = sqrtf(best[s]);
        ssum += r;
        rmin = fminf(rmin, r);
    }
    out[row] = log1pf((ssum - rmin) * 0.1f);   // mean over K=10 after dropping min
}

// ---------------------------------------------------------------------------
extern "C" void kernel_launch(void* const* d_in, const int* in_sizes, int n_in,
                              void* d_out, int out_size) {
    const float* x   = (const float*)d_in[0];
    const float* buf = (const float*)d_in[1];
    // x has 2048*64 = 131072 elements, buf has 131072*64; pick by size.
    if (n_in >= 2 && in_sizes[0] != N_X * D_DIM) {
        const float* t = x; x = buf; buf = t;
    }

    cudaFuncSetAttribute(pbe_main, cudaFuncAttributeMaxDynamicSharedMemorySize,
                         SMEM_FLOATS * (int)sizeof(float));

    bn2_kernel<<<M_BUF / 8, 256>>>(buf);
    pbe_main<<<dim3(N_X / BX, SPLITS), 256, SMEM_FLOATS * sizeof(float)>>>(x, buf);
    merge_kernel<<<N_X / 256, 256>>>((float*)d_out);
}

// round 3
// speedup vs baseline: 1.3892x; 1.3892x over previous
#include <cuda_runtime.h>
#include <cuda_bf16.h>
#include <math.h>
#include <float.h>
#include <stdint.h>

// ---------------- problem constants ----------------
#define N_X    2048
#define M_BUF  131072
#define D_DIM  64
#define KK     11                  // keep K+1 smallest
#define SPLITS 18
#define TILES_TOTAL (M_BUF / 128)  // 1024
#define TPS    57                  // ceil(1024/18) tiles per split
#define BX     128                 // x rows per CTA

// ---------------- device scratch ----------------
__device__ __nv_bfloat16 g_x16[N_X * D_DIM];
__device__ __nv_bfloat16 g_b16[(size_t)M_BUF * D_DIM];
__device__ float g_xn2[N_X];
__device__ float g_bn2[M_BUF];
__device__ float g_cand[(size_t)N_X * SPLITS * 4 * KK];

// ---------------- helpers ----------------
__device__ __forceinline__ uint32_t smem_u32(const void* p) {
    uint32_t a;
    asm("{ .reg .u64 t; cvta.to.shared.u64 t, %1; cvt.u32.u64 %0, t; }" : "=r"(a) : "l"(p));
    return a;
}
#define CP_ASYNC16(ds, gp) asm volatile("cp.async.cg.shared.global [%0], [%1], 16;" :: "r"(ds), "l"(gp))
#define CP_COMMIT() asm volatile("cp.async.commit_group;" ::: "memory")
#define CP_WAIT(n)  asm volatile("cp.async.wait_group %0;" :: "n"(n) : "memory")

#define LDSM_X4(r0, r1, r2, r3, a)                                             \
    asm volatile("ldmatrix.sync.aligned.m8n8.x4.shared.b16 {%0,%1,%2,%3}, [%4];"\
        : "=r"(r0), "=r"(r1), "=r"(r2), "=r"(r3) : "r"(a))

#define MMA_BF16(d, a, b0, b1)                                                 \
    asm volatile("mma.sync.aligned.m16n8k16.row.col.f32.bf16.bf16.f32 "        \
        "{%0,%1,%2,%3}, {%4,%5,%6,%7}, {%8,%9}, {%0,%1,%2,%3};"                \
        : "+f"((d)[0]), "+f"((d)[1]), "+f"((d)[2]), "+f"((d)[3])               \
        : "r"((a)[0]), "r"((a)[1]), "r"((a)[2]), "r"((a)[3]), "r"(b0), "r"(b1))

// ---------------- kernel 1: fp32 -> bf16 + squared norms ----------------
__global__ void prep_kernel(const float* __restrict__ x, const float* __restrict__ buf) {
    int gw = (blockIdx.x * blockDim.x + threadIdx.x) >> 5;
    int lane = threadIdx.x & 31;
    if (gw >= M_BUF + N_X) return;
    const float* src;
    __nv_bfloat16* dst;
    float* nrm;
    if (gw < M_BUF) { src = buf + (size_t)gw * D_DIM; dst = g_b16 + (size_t)gw * D_DIM; nrm = g_bn2 + gw; }
    else { int r = gw - M_BUF; src = x + (size_t)r * D_DIM; dst = g_x16 + (size_t)r * D_DIM; nrm = g_xn2 + r; }
    float2 v = reinterpret_cast<const float2*>(src)[lane];
    __nv_bfloat162 h;
    h.x = __float2bfloat16_rn(v.x);
    h.y = __float2bfloat16_rn(v.y);
    reinterpret_cast<__nv_bfloat162*>(dst)[lane] = h;
    float s = v.x * v.x + v.y * v.y;
    #pragma unroll
    for (int o = 16; o > 0; o >>= 1) s += __shfl_xor_sync(0xffffffffu, s, o);
    if (lane == 0) *nrm = s;
}

// ---------------- kernel 2: HMMA GEMM + fused running top-11 ----------------
// smem (bytes): xs 128x144 @0; b0 @18432; b1 @36864; bn0 @55296 (512B); bn1 @55808
#define XS_OFF  0
#define B0_OFF  18432
#define B1_OFF  36864
#define BN0_OFF 55296
#define BN1_OFF 55808
#define SMEM_TOTAL 56320
#define ROWB 144   // bytes per smem row (64 bf16 + 8 pad)

extern __shared__ unsigned char smem_raw[];

__device__ __forceinline__ void prefetch_tile(uint32_t sb, int tile, int buf_sel,
                                              int tid) {
    uint32_t boff = buf_sel ? B1_OFF : B0_OFF;
    const __nv_bfloat16* gbase = g_b16 + (size_t)tile * 128 * D_DIM;
    #pragma unroll
    for (int ii = 0; ii < 2; ii++) {
        int q = tid + 512 * ii;                 // 1024 chunks
        int row = q >> 3, qq = q & 7;
        CP_ASYNC16(sb + boff + row * ROWB + qq * 16,
                   gbase + (size_t)row * D_DIM + qq * 8);
    }
    if (tid < 32) {
        uint32_t bnoff = buf_sel ? BN1_OFF : BN0_OFF;
        CP_ASYNC16(sb + bnoff + tid * 16, g_bn2 + tile * 128 + tid * 4);
    }
}

__global__ void __launch_bounds__(512, 1)
pbe_mma() {
    const int tid = threadIdx.x;
    const int wid = tid >> 5;
    const int lid = tid & 31;
    const int warpM = wid >> 2;      // 0..3 -> 32 x rows each
    const int warpN = wid & 3;       // 0..3 -> 32 buf cols each
    const int xblock = blockIdx.x * BX;
    const int split  = blockIdx.y;
    const int tbeg = split * TPS;
    const int tend = min(tbeg + TPS, TILES_TOTAL);

    uint32_t sb = smem_u32(smem_raw);

    // ---- load x tile ----
    #pragma unroll
    for (int ii = 0; ii < 2; ii++) {
        int q = tid + 512 * ii;
        int row = q >> 3, qq = q & 7;
        CP_ASYNC16(sb + XS_OFF + row * ROWB + qq * 16,
                   g_x16 + (size_t)(xblock + row) * D_DIM + qq * 8);
    }
    CP_COMMIT();
    CP_WAIT(0);
    __syncthreads();

    // ---- A fragments, loaded ONCE (K=64 -> 4 k-steps x 2 m-frags) ----
    uint32_t afr[2][4][4];
    {
        int sub = lid >> 3, lr = lid & 7;
        #pragma unroll
        for (int mi = 0; mi < 2; mi++)
            #pragma unroll
            for (int ks = 0; ks < 4; ks++) {
                int row = warpM * 32 + mi * 16 + (sub & 1) * 8 + lr;
                int colb = (ks * 16 + (sub >> 1) * 8) * 2;
                uint32_t a = sb + XS_OFF + row * ROWB + colb;
                LDSM_X4(afr[mi][ks][0], afr[mi][ks][1], afr[mi][ks][2], afr[mi][ks][3], a);
            }
    }

    // xn2 for the 4 row-slots this lane owns
    const int g = lid >> 2;
    float xn2v[4];
    #pragma unroll
    for (int s = 0; s < 4; s++)
        xn2v[s] = g_xn2[xblock + warpM * 32 + (s >> 1) * 16 + (s & 1) * 8 + g];

    // running top-11 per row-slot
    float tk[4][KK];
    float thr[4];
    int   mxi[4];
    #pragma unroll
    for (int s = 0; s < 4; s++) {
        #pragma unroll
        for (int k = 0; k < KK; k++) tk[s][k] = FLT_MAX;
        thr[s] = FLT_MAX; mxi[s] = 0;
    }

    // ---- mainloop ----
    prefetch_tile(sb, tbeg, 0, tid);
    CP_COMMIT();

    for (int t = tbeg; t < tend; t++) {
        const int idx = t - tbeg;
        const int st = idx & 1;
        if (t + 1 < tend) {
            prefetch_tile(sb, t + 1, st ^ 1, tid);
            CP_COMMIT();
            CP_WAIT(1);
        } else {
            CP_WAIT(0);
        }
        __syncthreads();

        const uint32_t bt = sb + (st ? B1_OFF : B0_OFF);
        const uint32_t bn = sb + (st ? BN1_OFF : BN0_OFF);

        float acc[2][4][4];
        #pragma unroll
        for (int mi = 0; mi < 2; mi++)
            #pragma unroll
            for (int ni = 0; ni < 4; ni++)
                #pragma unroll
                for (int e = 0; e < 4; e++) acc[mi][ni][e] = 0.f;

        const int sub = lid >> 3, lr = lid & 7;
        #pragma unroll
        for (int ks = 0; ks < 4; ks++) {
            uint32_t bfr[2][4];
            #pragma unroll
            for (int np = 0; np < 2; np++) {
                int row = warpN * 32 + np * 16 + (sub >> 1) * 8 + lr;
                int colb = (ks * 16 + (sub & 1) * 8) * 2;
                uint32_t a = bt + row * ROWB + colb;
                LDSM_X4(bfr[np][0], bfr[np][1], bfr[np][2], bfr[np][3], a);
            }
            #pragma unroll
            for (int mi = 0; mi < 2; mi++) {
                MMA_BF16(acc[mi][0], afr[mi][ks], bfr[0][0], bfr[0][1]);
                MMA_BF16(acc[mi][1], afr[mi][ks], bfr[0][2], bfr[0][3]);
                MMA_BF16(acc[mi][2], afr[mi][ks], bfr[1][0], bfr[1][1]);
                MMA_BF16(acc[mi][3], afr[mi][ks], bfr[1][2], bfr[1][3]);
            }
        }

        // ---- epilogue: d2 + threshold-gated top-11 insert ----
        float2 bnp[4];
        #pragma unroll
        for (int ni = 0; ni < 4; ni++) {
            uint32_t a = bn + (warpN * 32 + ni * 8 + (lid & 3) * 2) * 4;
            asm volatile("ld.shared.v2.f32 {%0,%1}, [%2];"
                         : "=f"(bnp[ni].x), "=f"(bnp[ni].y) : "r"(a));
        }
        #pragma unroll
        for (int mi = 0; mi < 2; mi++)
            #pragma unroll
            for (int ni = 0; ni < 4; ni++)
                #pragma unroll
                for (int e = 0; e < 4; e++) {
                    const int s = mi * 2 + (e >> 1);
                    float bn2c = (e & 1) ? bnp[ni].y : bnp[ni].x;
                    float d2 = fmaf(-2.f, acc[mi][ni][e], xn2v[s] + bn2c);
                    d2 = fmaxf(d2, 0.f);
                    if (d2 < thr[s]) {
                        tk[s][mxi[s]] = d2;
                        float m = tk[s][0]; int mi2 = 0;
                        #pragma unroll
                        for (int k = 1; k < KK; k++)
                            if (tk[s][k] > m) { m = tk[s][k]; mi2 = k; }
                        thr[s] = m; mxi[s] = mi2;
                    }
                }
        __syncthreads();
    }

    // ---- cross-lane merge within each group of 4 lanes (same rows) ----
    #pragma unroll
    for (int s = 0; s < 4; s++) {
        #pragma unroll
        for (int c = 1; c < 4; c++) {
            #pragma unroll
            for (int k = 0; k < KK; k++) {
                float v = __shfl_sync(0xffffffffu, tk[s][k], (lid & ~3) | c);
                if ((lid & 3) == 0 && v < thr[s]) {
                    tk[s][mxi[s]] = v;
                    float m = tk[s][0]; int mi2 = 0;
                    #pragma unroll
                    for (int q = 1; q < KK; q++)
                        if (tk[s][q] > m) { m = tk[s][q]; mi2 = q; }
                    thr[s] = m; mxi[s] = mi2;
                }
            }
        }
    }
    if ((lid & 3) == 0) {
        #pragma unroll
        for (int s = 0; s < 4; s++) {
            int row = xblock + warpM * 32 + (s >> 1) * 16 + (s & 1) * 8 + g;
            float* dst = g_cand + (((size_t)row * SPLITS + split) * 4 + warpN) * KK;
            #pragma unroll
            for (int k = 0; k < KK; k++) dst[k] = tk[s][k];
        }
    }
}

// ---------------- kernel 3: merge, drop self-match, mean sqrt, log1p ---------
__global__ void merge_kernel(float* __restrict__ out) {
    int row = blockIdx.x * blockDim.x + threadIdx.x;
    if (row >= N_X) return;
    const float* src = g_cand + (size_t)row * SPLITS * 4 * KK;
    float best[KK];
    float m = FLT_MAX; int mi = 0;
    #pragma unroll
    for (int s = 0; s < KK; s++) best[s] = FLT_MAX;
    for (int s = 0; s < SPLITS * 4 * KK; s++) {
        float v = src[s];
        if (v < m) {
            best[mi] = v;
            float mm = best[0]; int mj = 0;
            #pragma unroll
            for (int q = 1; q < KK; q++)
                if (best[q] > mm) { mm = best[q]; mj = q; }
            m = mm; mi = mj;
        }
    }
    float ssum = 0.f, rmin = FLT_MAX;
    #pragma unroll
    for (int s = 0; s < KK; s++) {
        float r = sqrtf(fmaxf(best[s], 0.f));
        ssum += r;
        rmin = fminf(rmin, r);
    }
    out[row] = log1pf((ssum - rmin) * 0.1f);
}

// ---------------------------------------------------------------------------
extern "C" void kernel_launch(void* const* d_in, const int* in_sizes, int n_in,
                              void* d_out, int out_size) {
    const float* x   = (const float*)d_in[0];
    const float* buf = (const float*)d_in[1];
    if (n_in >= 2 && in_sizes[0] != N_X * D_DIM) {
        const float* t = x; x = buf; buf = t;
    }

    cudaFuncSetAttribute(pbe_mma, cudaFuncAttributeMaxDynamicSharedMemorySize, SMEM_TOTAL);

    int total_warps = M_BUF + N_X;
    prep_kernel<<<(total_warps * 32 + 255) / 256, 256>>>(x, buf);
    pbe_mma<<<dim3(N_X / BX, SPLITS), 512, SMEM_TOTAL>>>();
    merge_kernel<<<(N_X + 255) / 256, 256>>>((float*)d_out);
}